// round 2
// baseline (speedup 1.0000x reference)
#include <cuda_runtime.h>

// ---------------- problem constants (fixed by the dataset) ----------------
#define NA 8      // agents
#define BB 32     // batch per agent
#define NB 256    // NA*BB
#define FF 256    // features
#define TT 64     // seq (token axis)
#define HH 8      // heads
#define DD 32     // head dim
#define SCALE 0.0625f  // 1/sqrt(FF)

// ---------------- scratch (device globals; no allocations allowed) --------
__device__ float g_q[HH*NA*BB*TT*DD];   // [h][n][b][t][d]
__device__ float g_k[HH*NA*BB*TT*DD];
__device__ float g_v[HH*NA*BB*TT*DD];
__device__ float g_y[NB*FF*TT];         // [nb][f][t], f = h*32+d

// ---------------- packed fp32x2 helpers (Blackwell FFMA2) -----------------
typedef unsigned long long u64;

__device__ __forceinline__ u64 dup2(float x) {
    u64 r;
    asm("mov.b64 %0, {%1, %1};" : "=l"(r) : "f"(x));
    return r;
}
__device__ __forceinline__ void unpack2(u64 v, float& lo, float& hi) {
    asm("mov.b64 {%0, %1}, %2;" : "=f"(lo), "=f"(hi) : "l"(v));
}
__device__ __forceinline__ u64 fma2(u64 a, u64 b, u64 c) {
    u64 d;
    asm("fma.rn.f32x2 %0, %1, %2, %3;" : "=l"(d) : "l"(a), "l"(b), "l"(c));
    return d;
}
// 16B shared load straight into two packed-f32x2 registers
__device__ __forceinline__ void lds_v2u64(const float* p, u64& a, u64& b) {
    u64 addr = (u64)__cvta_generic_to_shared(p);
    asm("ld.shared.v2.u64 {%0, %1}, [%2];" : "=l"(a), "=l"(b) : "l"(addr));
}

// ======================== kernel 1: QKV projections ========================
// grid = 768 (mat*256 + nb), block = 256.
// out[h][n][b][t][d] = sum_f x[nb][f][t] * W[h][f][d]
__global__ void __launch_bounds__(256) qkv_kernel(
    const float* __restrict__ x,
    const float* __restrict__ Wq,
    const float* __restrict__ Wk,
    const float* __restrict__ Wv)
{
    __shared__ __align__(16) float xs[128 * TT];   // 32 KB: half of x[nb], [f][t]

    const int bid = blockIdx.x;
    const int nb  = bid & 255;
    const int mat = bid >> 8;            // 0=q, 1=k, 2=v
    const float* W  = (mat == 0) ? Wq : (mat == 1) ? Wk : Wv;
    float* outg     = (mat == 0) ? g_q : (mat == 1) ? g_k : g_v;

    const int tid = threadIdx.x;
    const int h   = tid >> 5;
    const int d   = tid & 31;

    u64 acc[32];
    #pragma unroll
    for (int i = 0; i < 32; i++) acc[i] = 0ull;   // bit pattern of (0.f,0.f)

    const float* xb   = x + (size_t)nb * (FF * TT);
    const float* wcol = W + h * (FF * DD) + d;

    for (int chunk = 0; chunk < 2; chunk++) {
        __syncthreads();
        {   // stage 128x64 floats, coalesced
            const float4* src = (const float4*)(xb + chunk * 128 * TT);
            float4* dst = (float4*)xs;
            #pragma unroll
            for (int i = 0; i < 8; i++) dst[tid + i * 256] = src[tid + i * 256];
        }
        __syncthreads();

        const float* wc = wcol + chunk * 128 * DD;
        #pragma unroll 4
        for (int fl = 0; fl < 128; fl++) {
            u64 w2 = dup2(wc[fl * DD]);            // coalesced across warp
            const float* row = xs + fl * TT;
            #pragma unroll
            for (int u = 0; u < 16; u++) {         // 64 t as 16x (v2.u64)
                u64 a, b;
                lds_v2u64(row + 4 * u, a, b);      // broadcast
                acc[2 * u]     = fma2(a, w2, acc[2 * u]);
                acc[2 * u + 1] = fma2(b, w2, acc[2 * u + 1]);
            }
        }
    }

    // write: [h][n][b][t][d]
    const int n = nb >> 5, b = nb & 31;
    float* o = outg + (size_t)(((h * NA + n) * BB + b) * TT) * DD + d;
    #pragma unroll
    for (int j = 0; j < 32; j++) {
        float a, bv; unpack2(acc[j], a, bv);
        o[(2 * j) * DD]     = a;                   // coalesced per-t
        o[(2 * j + 1) * DD] = bv;
    }
}

// ======================== kernel 2: all-pairs attention ====================
// grid = 2048 (h*256 + j*32 + b), block = 256.
// For query agent j: for each key agent i: S = q_j k_i^T * scale (t x s),
// row-softmax over s, out += P @ v_i. Write to g_y[nb][h*32+d][t].
__global__ void __launch_bounds__(256, 2) attn_kernel()
{
    __shared__ __align__(16) float kT[DD * 66];    // [d][s], pad 66
    __shared__ __align__(16) float vs[TT * DD];    // [s][d]
    __shared__ __align__(16) float P [TT * 66];    // [t][s], pad 66

    const int bid = blockIdx.x;
    const int b = bid & 31, j = (bid >> 5) & 7, h = bid >> 8;
    const int tid = threadIdx.x;
    const int t0  = tid >> 3;       // rows t0 and t0+32
    const int c8  = tid & 7;        // 8-way column split

    // q rows in registers, pre-scaled
    float qa[32], qb2[32];
    {
        const float* qb = g_q + (size_t)(((h * NA + j) * BB + b) * TT) * DD;
        const float4* ra = (const float4*)(qb + t0 * DD);
        const float4* rb = (const float4*)(qb + (t0 + 32) * DD);
        #pragma unroll
        for (int i = 0; i < 8; i++) {
            float4 a4 = ra[i], b4 = rb[i];
            qa[4*i+0] = a4.x * SCALE; qa[4*i+1] = a4.y * SCALE;
            qa[4*i+2] = a4.z * SCALE; qa[4*i+3] = a4.w * SCALE;
            qb2[4*i+0] = b4.x * SCALE; qb2[4*i+1] = b4.y * SCALE;
            qb2[4*i+2] = b4.z * SCALE; qb2[4*i+3] = b4.w * SCALE;
        }
    }

    u64 outA[2] = {0ull, 0ull}, outB[2] = {0ull, 0ull};

    for (int i = 0; i < NA; i++) {
        __syncthreads();   // protect smem reuse from previous iteration
        {
            const float* kb = g_k + (size_t)(((h * NA + i) * BB + b) * TT) * DD;
            const float* vb = g_v + (size_t)(((h * NA + i) * BB + b) * TT) * DD;
            #pragma unroll
            for (int r = 0; r < 8; r++) {
                int idx = tid + r * 256;
                int s = idx >> 5, d = idx & 31;
                kT[d * 66 + s] = kb[idx];          // transposed store
                vs[idx]        = vb[idx];          // linear
            }
        }
        __syncthreads();

        // ---- S = q @ k^T : 4 s-pairs per row, s0 = 2*c8 + 16*m ----
        u64 sA[4] = {0ull,0ull,0ull,0ull}, sB[4] = {0ull,0ull,0ull,0ull};
        #pragma unroll 8
        for (int d = 0; d < DD; d++) {
            const u64* kr = (const u64*)(kT + d * 66);
            u64 k0 = kr[c8], k1 = kr[c8 + 8], k2 = kr[c8 + 16], k3 = kr[c8 + 24];
            u64 qda = dup2(qa[d]);
            u64 qdb = dup2(qb2[d]);
            sA[0] = fma2(k0, qda, sA[0]); sA[1] = fma2(k1, qda, sA[1]);
            sA[2] = fma2(k2, qda, sA[2]); sA[3] = fma2(k3, qda, sA[3]);
            sB[0] = fma2(k0, qdb, sB[0]); sB[1] = fma2(k1, qdb, sB[1]);
            sB[2] = fma2(k2, qdb, sB[2]); sB[3] = fma2(k3, qdb, sB[3]);
        }

        // ---- softmax over s (per key agent i), rows t0 and t0+32 ----
        float eA[8], eB[8];
        #pragma unroll
        for (int m = 0; m < 4; m++) {
            unpack2(sA[m], eA[2*m], eA[2*m+1]);
            unpack2(sB[m], eB[2*m], eB[2*m+1]);
        }
        float mA = eA[0], mB = eB[0];
        #pragma unroll
        for (int p = 1; p < 8; p++) { mA = fmaxf(mA, eA[p]); mB = fmaxf(mB, eB[p]); }
        #pragma unroll
        for (int w = 1; w < 8; w <<= 1) {
            mA = fmaxf(mA, __shfl_xor_sync(0xffffffffu, mA, w));
            mB = fmaxf(mB, __shfl_xor_sync(0xffffffffu, mB, w));
        }
        float sumA = 0.f, sumB = 0.f;
        #pragma unroll
        for (int p = 0; p < 8; p++) {
            eA[p] = __expf(eA[p] - mA); sumA += eA[p];
            eB[p] = __expf(eB[p] - mB); sumB += eB[p];
        }
        #pragma unroll
        for (int w = 1; w < 8; w <<= 1) {
            sumA += __shfl_xor_sync(0xffffffffu, sumA, w);
            sumB += __shfl_xor_sync(0xffffffffu, sumB, w);
        }
        float invA = __frcp_rn(sumA), invB = __frcp_rn(sumB);

        float* Pa = P + t0 * 66;
        float* Pb = P + (t0 + 32) * 66;
        #pragma unroll
        for (int m = 0; m < 4; m++) {
            ((float2*)Pa)[c8 + 8*m] = make_float2(eA[2*m] * invA, eA[2*m+1] * invA);
            ((float2*)Pb)[c8 + 8*m] = make_float2(eB[2*m] * invB, eB[2*m+1] * invB);
        }
        __syncwarp();   // P rows are warp-local (4 lanes per row, same warp)

        // ---- out += P @ V : this thread owns d = 4*c8 .. 4*c8+3 ----
        #pragma unroll 4
        for (int s2 = 0; s2 < 32; s2++) {
            float2 pA = ((const float2*)Pa)[s2];
            float2 pB = ((const float2*)Pb)[s2];
            u64 va0, va1, vb0, vb1;
            lds_v2u64(vs + (2 * s2)     * DD + 4 * c8, va0, va1);
            lds_v2u64(vs + (2 * s2 + 1) * DD + 4 * c8, vb0, vb1);
            u64 pA0 = dup2(pA.x), pA1 = dup2(pA.y);
            u64 pB0 = dup2(pB.x), pB1 = dup2(pB.y);
            outA[0] = fma2(va0, pA0, outA[0]); outA[1] = fma2(va1, pA0, outA[1]);
            outA[0] = fma2(vb0, pA1, outA[0]); outA[1] = fma2(vb1, pA1, outA[1]);
            outB[0] = fma2(va0, pB0, outB[0]); outB[1] = fma2(va1, pB0, outB[1]);
            outB[0] = fma2(vb0, pB1, outB[0]); outB[1] = fma2(vb1, pB1, outB[1]);
        }
        __syncwarp();
    }

    // write y[nb][h*32+d][t]
    const int nb = j * BB + b;
    float* yo = g_y + (size_t)(nb * FF + h * DD + 4 * c8) * TT + t0;
    float x0, x1, x2, x3;
    unpack2(outA[0], x0, x1); unpack2(outA[1], x2, x3);
    yo[0] = x0; yo[TT] = x1; yo[2*TT] = x2; yo[3*TT] = x3;
    unpack2(outB[0], x0, x1); unpack2(outB[1], x2, x3);
    float* yo2 = yo + 32;
    yo2[0] = x0; yo2[TT] = x1; yo2[2*TT] = x2; yo2[3*TT] = x3;
}

// ======================== kernel 3: output projection ======================
// grid = 256 (nb), block = 256.
// out[nb][g][t] = sum_f y[nb][f][t] * Wp[g][f] + bp[g]
__global__ void __launch_bounds__(256) proj_kernel(
    const float* __restrict__ Wp,
    const float* __restrict__ bp,
    float* __restrict__ out)
{
    __shared__ __align__(16) float ys[128 * TT];   // 32 KB

    const int nb = blockIdx.x;
    const int g  = threadIdx.x;

    u64 acc[32];
    #pragma unroll
    for (int i = 0; i < 32; i++) acc[i] = 0ull;

    const float* yb = g_y + (size_t)nb * (FF * TT);

    for (int chunk = 0; chunk < 2; chunk++) {
        __syncthreads();
        {
            const float4* src = (const float4*)(yb + chunk * 128 * TT);
            float4* dst = (float4*)ys;
            #pragma unroll
            for (int i = 0; i < 8; i++) dst[g + i * 256] = src[g + i * 256];
        }
        __syncthreads();

        const float4* wr = (const float4*)(Wp + g * FF + chunk * 128);
        #pragma unroll 2
        for (int f4 = 0; f4 < 32; f4++) {
            float4 w4 = wr[f4];
            const float wv[4] = {w4.x, w4.y, w4.z, w4.w};
            #pragma unroll
            for (int sub = 0; sub < 4; sub++) {
                u64 w2 = dup2(wv[sub]);
                const float* row = ys + (f4 * 4 + sub) * TT;
                #pragma unroll
                for (int u = 0; u < 16; u++) {
                    u64 a, b;
                    lds_v2u64(row + 4 * u, a, b);
                    acc[2 * u]     = fma2(a, w2, acc[2 * u]);
                    acc[2 * u + 1] = fma2(b, w2, acc[2 * u + 1]);
                }
            }
        }
    }

    const float bpv = bp[g];
    float* o = out + (size_t)(nb * FF + g) * TT;
    #pragma unroll
    for (int j = 0; j < 32; j++) {
        float a, bv; unpack2(acc[j], a, bv);
        ((float2*)o)[j] = make_float2(a + bpv, bv + bpv);
    }
}

// ======================== launch ==========================================
extern "C" void kernel_launch(void* const* d_in, const int* in_sizes, int n_in,
                              void* d_out, int out_size)
{
    (void)in_sizes; (void)n_in; (void)out_size;
    const float* x  = (const float*)d_in[0];
    const float* Wq = (const float*)d_in[1];
    const float* Wk = (const float*)d_in[2];
    const float* Wv = (const float*)d_in[3];
    const float* Wp = (const float*)d_in[4];
    const float* bp = (const float*)d_in[5];
    float* out = (float*)d_out;

    qkv_kernel<<<768, 256>>>(x, Wq, Wk, Wv);
    attn_kernel<<<2048, 256>>>();
    proj_kernel<<<256, 256>>>(Wp, bp, out);
}

// round 3
// speedup vs baseline: 1.2129x; 1.2129x over previous
#include <cuda_runtime.h>

// ---------------- problem constants (fixed by the dataset) ----------------
#define NA 8      // agents
#define BB 32     // batch per agent
#define NB 256    // NA*BB
#define FF 256    // features
#define TT 64     // seq (token axis)
#define HH 8      // heads
#define DD 32     // head dim
#define SCALE 0.0625f  // 1/sqrt(FF)

// ---------------- scratch (device globals; no allocations allowed) --------
__device__ float g_q[HH*NA*BB*TT*DD];   // [h][n][b][t][d]
__device__ float g_k[HH*NA*BB*TT*DD];
__device__ float g_v[HH*NA*BB*TT*DD];
__device__ float g_y[NB*FF*TT];         // [nb][f][t], f = h*32+d

// ---------------- packed fp32x2 helpers (Blackwell FFMA2) -----------------
typedef unsigned long long u64;

__device__ __forceinline__ u64 dup2(float x) {
    u64 r;
    asm("mov.b64 %0, {%1, %1};" : "=l"(r) : "f"(x));
    return r;
}
__device__ __forceinline__ void unpack2(u64 v, float& lo, float& hi) {
    asm("mov.b64 {%0, %1}, %2;" : "=f"(lo), "=f"(hi) : "l"(v));
}
__device__ __forceinline__ u64 fma2(u64 a, u64 b, u64 c) {
    u64 d;
    asm("fma.rn.f32x2 %0, %1, %2, %3;" : "=l"(d) : "l"(a), "l"(b), "l"(c));
    return d;
}
// 16B shared load straight into two packed-f32x2 registers
__device__ __forceinline__ void lds_v2u64(const float* p, u64& a, u64& b) {
    u64 addr = (u64)__cvta_generic_to_shared(p);
    asm("ld.shared.v2.u64 {%0, %1}, [%2];" : "=l"(a), "=l"(b) : "l"(addr));
}

// ======================== kernel 1: QKV projections ========================
// grid = 768 (mat*256 + nb), block = 256.
// out[h][n][b][t][d] = sum_f x[nb][f][t] * W[h][f][d]
// Thread (fg = tid&31, tg = tid>>5): outputs fout = fg + 32k (k = head),
// t = tg*8 .. tg*8+7.  8 fout x 8 t = 64 outputs (32 u64 accs).
__global__ void __launch_bounds__(256, 2) qkv_kernel(
    const float* __restrict__ x,
    const float* __restrict__ Wq,
    const float* __restrict__ Wk,
    const float* __restrict__ Wv)
{
    __shared__ __align__(16) float xs[32 * 64];     // [fl][t]   8 KB
    __shared__ __align__(16) float ws[32 * 257];    // [fl][fout], 257-pad  32.1 KB

    const int bid = blockIdx.x;
    const int nb  = bid & 255;
    const int mat = bid >> 8;            // 0=q, 1=k, 2=v
    const float* W  = (mat == 0) ? Wq : (mat == 1) ? Wk : Wv;
    float* outg     = (mat == 0) ? g_q : (mat == 1) ? g_k : g_v;

    const int tid = threadIdx.x;
    const int fg  = tid & 31;
    const int tg  = tid >> 5;
    const int t0  = tg * 8;

    u64 acc[8][4];
    #pragma unroll
    for (int k = 0; k < 8; k++)
        #pragma unroll
        for (int p = 0; p < 4; p++) acc[k][p] = 0ull;

    const float* xb = x + (size_t)nb * (FF * TT);

    for (int c = 0; c < 8; c++) {
        const int f0 = c * 32;
        __syncthreads();
        {   // stage x chunk: rows f0..f0+31, contiguous 2048 floats
            const float4* s4 = (const float4*)(xb + f0 * TT);
            float4* d4 = (float4*)xs;
            d4[tid]       = s4[tid];
            d4[tid + 256] = s4[tid + 256];
        }
        {   // stage W chunk into ws[fl][h*32+d] with 257-pad rows
            #pragma unroll
            for (int m = 0; m < 8; m++) {
                int jj = tid + m * 256;            // 0..2047 (float4 index)
                int h  = jj >> 8;
                int r  = jj & 255;                 // float4 idx within h block
                int fl = r >> 3;
                int d0 = (r & 7) * 4;
                float4 wv = ((const float4*)(W + h * (FF * DD) + f0 * DD))[r];
                float* dst = ws + fl * 257 + h * 32 + d0;
                dst[0] = wv.x; dst[1] = wv.y; dst[2] = wv.z; dst[3] = wv.w;
            }
        }
        __syncthreads();

        #pragma unroll 2
        for (int fl = 0; fl < 32; fl++) {
            u64 xp[4];
            lds_v2u64(xs + fl * 64 + t0, xp[0], xp[1]);
            lds_v2u64(xs + fl * 64 + t0 + 4, xp[2], xp[3]);
            const float* wrow = ws + fl * 257 + fg;
            #pragma unroll
            for (int k = 0; k < 8; k++) {
                u64 wd = dup2(wrow[k * 32]);
                acc[k][0] = fma2(xp[0], wd, acc[k][0]);
                acc[k][1] = fma2(xp[1], wd, acc[k][1]);
                acc[k][2] = fma2(xp[2], wd, acc[k][2]);
                acc[k][3] = fma2(xp[3], wd, acc[k][3]);
            }
        }
    }

    // write: [h][n][b][t][d], h = k, d = fg; coalesced (lanes span d)
    const int n = nb >> 5, b = nb & 31;
    #pragma unroll
    for (int k = 0; k < 8; k++) {
        float* o = outg + (size_t)(((k * NA + n) * BB + b) * TT) * DD + fg;
        #pragma unroll
        for (int p = 0; p < 4; p++) {
            float a, bv; unpack2(acc[k][p], a, bv);
            o[(t0 + 2 * p)     * DD] = a;
            o[(t0 + 2 * p + 1) * DD] = bv;
        }
    }
}

// ======================== kernel 2: all-pairs attention ====================
// grid = 2048 (h*256 + j*32 + b), block = 256.
// q in smem (scaled); k/v prefetched to regs for i+1 during compute of i.
__global__ void __launch_bounds__(256, 2) attn_kernel()
{
    __shared__ __align__(16) float kT[DD * 66];    // [d][s], pad 66   8.4 KB
    __shared__ __align__(16) float vs[TT * DD];    // [s][d]           8 KB
    __shared__ __align__(16) float Ps[TT * 66];    // [t][s], pad 66  16.9 KB
    __shared__ __align__(16) float qs[TT * 33];    // [t][d], pad 33   8.4 KB

    const int bid = blockIdx.x;
    const int b = bid & 31, j = (bid >> 5) & 7, h = bid >> 8;
    const int tid = threadIdx.x;
    const int t0  = tid >> 3;       // rows t0 and t0+32
    const int c8  = tid & 7;        // 8-way column split

    // stage q (pre-scaled) into smem
    {
        const float* qb = g_q + (size_t)(((h * NA + j) * BB + b) * TT) * DD;
        #pragma unroll
        for (int r = 0; r < 8; r++) {
            int idx = tid + r * 256;
            int t = idx >> 5, d = idx & 31;
            qs[t * 33 + d] = qb[idx] * SCALE;
        }
    }

    u64 outA[2] = {0ull, 0ull}, outB[2] = {0ull, 0ull};

    const size_t kvstride4 = (size_t)BB * TT * DD / 4;   // float4 stride per i
    const float4* kb4 = (const float4*)(g_k + (size_t)((h * NA) * BB + b) * TT * DD);
    const float4* vb4 = (const float4*)(g_v + (size_t)((h * NA) * BB + b) * TT * DD);

    // prefetch i = 0
    float4 k4[2], v4[2];
    k4[0] = kb4[tid]; k4[1] = kb4[tid + 256];
    v4[0] = vb4[tid]; v4[1] = vb4[tid + 256];

    for (int i = 0; i < NA; i++) {
        __syncthreads();   // previous compute done -> buffers free; qs visible path
        {   // store staged k (transposed) and v
            #pragma unroll
            for (int m = 0; m < 2; m++) {
                int jj = tid + m * 256;
                int s = jj >> 3, d0 = (jj & 7) * 4;
                float4 kv = k4[m];
                kT[(d0 + 0) * 66 + s] = kv.x;
                kT[(d0 + 1) * 66 + s] = kv.y;
                kT[(d0 + 2) * 66 + s] = kv.z;
                kT[(d0 + 3) * 66 + s] = kv.w;
                ((float4*)vs)[jj] = v4[m];
            }
        }
        __syncthreads();

        if (i < NA - 1) {   // prefetch next i; latency hidden by compute below
            const float4* nk = kb4 + (size_t)(i + 1) * kvstride4;
            const float4* nv = vb4 + (size_t)(i + 1) * kvstride4;
            k4[0] = nk[tid]; k4[1] = nk[tid + 256];
            v4[0] = nv[tid]; v4[1] = nv[tid + 256];
        }

        // ---- S = q @ k^T : 4 s-pairs per row, rows t0 and t0+32 ----
        u64 sA[4] = {0ull,0ull,0ull,0ull}, sB[4] = {0ull,0ull,0ull,0ull};
        #pragma unroll 8
        for (int d = 0; d < DD; d++) {
            const u64* kr = (const u64*)(kT + d * 66);
            u64 k0 = kr[c8], k1 = kr[c8 + 8], k2 = kr[c8 + 16], k3 = kr[c8 + 24];
            u64 qda = dup2(qs[t0 * 33 + d]);
            u64 qdb = dup2(qs[(t0 + 32) * 33 + d]);
            sA[0] = fma2(k0, qda, sA[0]); sA[1] = fma2(k1, qda, sA[1]);
            sA[2] = fma2(k2, qda, sA[2]); sA[3] = fma2(k3, qda, sA[3]);
            sB[0] = fma2(k0, qdb, sB[0]); sB[1] = fma2(k1, qdb, sB[1]);
            sB[2] = fma2(k2, qdb, sB[2]); sB[3] = fma2(k3, qdb, sB[3]);
        }

        // ---- softmax over s (per key agent i) ----
        float eA[8], eB[8];
        #pragma unroll
        for (int m = 0; m < 4; m++) {
            unpack2(sA[m], eA[2*m], eA[2*m+1]);
            unpack2(sB[m], eB[2*m], eB[2*m+1]);
        }
        float mA = eA[0], mB = eB[0];
        #pragma unroll
        for (int p = 1; p < 8; p++) { mA = fmaxf(mA, eA[p]); mB = fmaxf(mB, eB[p]); }
        #pragma unroll
        for (int w = 1; w < 8; w <<= 1) {
            mA = fmaxf(mA, __shfl_xor_sync(0xffffffffu, mA, w));
            mB = fmaxf(mB, __shfl_xor_sync(0xffffffffu, mB, w));
        }
        float sumA = 0.f, sumB = 0.f;
        #pragma unroll
        for (int p = 0; p < 8; p++) {
            eA[p] = __expf(eA[p] - mA); sumA += eA[p];
            eB[p] = __expf(eB[p] - mB); sumB += eB[p];
        }
        #pragma unroll
        for (int w = 1; w < 8; w <<= 1) {
            sumA += __shfl_xor_sync(0xffffffffu, sumA, w);
            sumB += __shfl_xor_sync(0xffffffffu, sumB, w);
        }
        float invA = __frcp_rn(sumA), invB = __frcp_rn(sumB);

        float* Pa = Ps + t0 * 66;
        float* Pb = Ps + (t0 + 32) * 66;
        #pragma unroll
        for (int m = 0; m < 4; m++) {
            ((float2*)Pa)[c8 + 8*m] = make_float2(eA[2*m] * invA, eA[2*m+1] * invA);
            ((float2*)Pb)[c8 + 8*m] = make_float2(eB[2*m] * invB, eB[2*m+1] * invB);
        }
        __syncwarp();   // P rows are warp-local

        // ---- out += P @ V : this thread owns d = 4*c8 .. 4*c8+3 ----
        #pragma unroll 4
        for (int s2 = 0; s2 < 32; s2++) {
            float2 pA = ((const float2*)Pa)[s2];
            float2 pB = ((const float2*)Pb)[s2];
            u64 va0, va1, vb0, vb1;
            lds_v2u64(vs + (2 * s2)     * DD + 4 * c8, va0, va1);
            lds_v2u64(vs + (2 * s2 + 1) * DD + 4 * c8, vb0, vb1);
            u64 pA0 = dup2(pA.x), pA1 = dup2(pA.y);
            u64 pB0 = dup2(pB.x), pB1 = dup2(pB.y);
            outA[0] = fma2(va0, pA0, outA[0]); outA[1] = fma2(va1, pA0, outA[1]);
            outA[0] = fma2(vb0, pA1, outA[0]); outA[1] = fma2(vb1, pA1, outA[1]);
            outB[0] = fma2(va0, pB0, outB[0]); outB[1] = fma2(va1, pB0, outB[1]);
            outB[0] = fma2(vb0, pB1, outB[0]); outB[1] = fma2(vb1, pB1, outB[1]);
        }
        __syncwarp();
    }

    // write y[nb][h*32+d][t]
    const int nb = j * BB + b;
    float* yo = g_y + (size_t)(nb * FF + h * DD + 4 * c8) * TT + t0;
    float x0, x1, x2, x3;
    unpack2(outA[0], x0, x1); unpack2(outA[1], x2, x3);
    yo[0] = x0; yo[TT] = x1; yo[2*TT] = x2; yo[3*TT] = x3;
    unpack2(outB[0], x0, x1); unpack2(outB[1], x2, x3);
    float* yo2 = yo + 32;
    yo2[0] = x0; yo2[TT] = x1; yo2[2*TT] = x2; yo2[3*TT] = x3;
}

// ======================== kernel 3: output projection ======================
// grid = 256 (nb), block = 256.
// out[nb][g][t] = sum_f y[nb][f][t] * Wp[g][f] + bp[g]
// Thread (fg, tg): g = fg + 32k, t = tg*8..tg*8+7.
__global__ void __launch_bounds__(256, 2) proj_kernel(
    const float* __restrict__ Wp,
    const float* __restrict__ bp,
    float* __restrict__ out)
{
    __shared__ __align__(16) float ys[32 * 64];     // [fl][t]
    __shared__ __align__(16) float ws[32 * 257];    // [fl][g], 257-pad

    const int nb  = blockIdx.x;
    const int tid = threadIdx.x;
    const int fg  = tid & 31;
    const int tg  = tid >> 5;
    const int t0  = tg * 8;

    u64 acc[8][4];
    #pragma unroll
    for (int k = 0; k < 8; k++)
        #pragma unroll
        for (int p = 0; p < 4; p++) acc[k][p] = 0ull;

    const float* yb = g_y + (size_t)nb * (FF * TT);

    for (int c = 0; c < 8; c++) {
        const int f0 = c * 32;
        __syncthreads();
        {   // stage y chunk (contiguous)
            const float4* s4 = (const float4*)(yb + f0 * TT);
            float4* d4 = (float4*)ys;
            d4[tid]       = s4[tid];
            d4[tid + 256] = s4[tid + 256];
        }
        {   // stage Wp chunk transposed: ws[fl][g] = Wp[g][f0+fl]
            #pragma unroll
            for (int m = 0; m < 8; m++) {
                int jj = tid + m * 256;           // float4 index, 0..2047
                int g   = jj >> 3;
                int fl0 = (jj & 7) * 4;
                float4 wv = ((const float4*)(Wp + g * FF + f0))[jj & 7];
                ws[(fl0 + 0) * 257 + g] = wv.x;
                ws[(fl0 + 1) * 257 + g] = wv.y;
                ws[(fl0 + 2) * 257 + g] = wv.z;
                ws[(fl0 + 3) * 257 + g] = wv.w;
            }
        }
        __syncthreads();

        #pragma unroll 2
        for (int fl = 0; fl < 32; fl++) {
            u64 xp[4];
            lds_v2u64(ys + fl * 64 + t0, xp[0], xp[1]);
            lds_v2u64(ys + fl * 64 + t0 + 4, xp[2], xp[3]);
            const float* wrow = ws + fl * 257 + fg;
            #pragma unroll
            for (int k = 0; k < 8; k++) {
                u64 wd = dup2(wrow[k * 32]);
                acc[k][0] = fma2(xp[0], wd, acc[k][0]);
                acc[k][1] = fma2(xp[1], wd, acc[k][1]);
                acc[k][2] = fma2(xp[2], wd, acc[k][2]);
                acc[k][3] = fma2(xp[3], wd, acc[k][3]);
            }
        }
    }

    #pragma unroll
    for (int k = 0; k < 8; k++) {
        const int g = fg + 32 * k;
        const float bpv = bp[g];
        float* o = out + (size_t)(nb * FF + g) * TT + t0;
        #pragma unroll
        for (int p = 0; p < 4; p++) {
            float a, bv; unpack2(acc[k][p], a, bv);
            ((float2*)o)[p] = make_float2(a + bpv, bv + bpv);
        }
    }
}

// ======================== launch ==========================================
extern "C" void kernel_launch(void* const* d_in, const int* in_sizes, int n_in,
                              void* d_out, int out_size)
{
    (void)in_sizes; (void)n_in; (void)out_size;
    const float* x  = (const float*)d_in[0];
    const float* Wq = (const float*)d_in[1];
    const float* Wk = (const float*)d_in[2];
    const float* Wv = (const float*)d_in[3];
    const float* Wp = (const float*)d_in[4];
    const float* bp = (const float*)d_in[5];
    float* out = (float*)d_out;

    qkv_kernel<<<768, 256>>>(x, Wq, Wk, Wv);
    attn_kernel<<<2048, 256>>>();
    proj_kernel<<<256, 256>>>(Wp, bp, out);
}

// round 4
// speedup vs baseline: 1.2151x; 1.0019x over previous
#include <cuda_runtime.h>

// ---------------- problem constants (fixed by the dataset) ----------------
#define NA 8      // agents
#define BB 32     // batch per agent
#define NB 256    // NA*BB
#define FF 256    // features
#define TT 64     // seq (token axis)
#define HH 8      // heads
#define DD 32     // head dim
#define SCALE 0.0625f  // 1/sqrt(FF)

// ---------------- scratch (device globals; no allocations allowed) --------
__device__ float g_q[HH*NA*BB*TT*DD];   // [h][n][b][t][d]
__device__ float g_k[HH*NA*BB*TT*DD];
__device__ float g_v[HH*NA*BB*TT*DD];
__device__ float g_y[NB*FF*TT];         // [nb][f][t], f = h*32+d

// ---------------- packed fp32x2 helpers (Blackwell FFMA2) -----------------
typedef unsigned long long u64;

__device__ __forceinline__ u64 dup2(float x) {
    u64 r;
    asm("mov.b64 %0, {%1, %1};" : "=l"(r) : "f"(x));
    return r;
}
__device__ __forceinline__ void unpack2(u64 v, float& lo, float& hi) {
    asm("mov.b64 {%0, %1}, %2;" : "=f"(lo), "=f"(hi) : "l"(v));
}
__device__ __forceinline__ u64 fma2(u64 a, u64 b, u64 c) {
    u64 d;
    asm("fma.rn.f32x2 %0, %1, %2, %3;" : "=l"(d) : "l"(a), "l"(b), "l"(c));
    return d;
}
// 16B shared load straight into two packed-f32x2 registers
__device__ __forceinline__ void lds_v2u64(const float* p, u64& a, u64& b) {
    u64 addr = (u64)__cvta_generic_to_shared(p);
    asm("ld.shared.v2.u64 {%0, %1}, [%2];" : "=l"(a), "=l"(b) : "l"(addr));
}

// ======================== kernel 1: QKV projections ========================
// grid = 768 (mat*256 + nb), block = 256.
// out[h][n][b][t][d] = sum_f x[nb][f][t] * W[h][f][d]
// Thread (fg = tid&31, tg = tid>>5): outputs fout = fg + 32k (k = head),
// t = tg*8 .. tg*8+7.  8 fout x 8 t = 64 outputs (32 u64 accs).
__global__ void __launch_bounds__(256, 2) qkv_kernel(
    const float* __restrict__ x,
    const float* __restrict__ Wq,
    const float* __restrict__ Wk,
    const float* __restrict__ Wv)
{
    __shared__ __align__(16) float xs[32 * 64];     // [fl][t]   8 KB
    __shared__ __align__(16) float ws[32 * 257];    // [fl][fout], 257-pad  32.1 KB

    const int bid = blockIdx.x;
    const int nb  = bid & 255;
    const int mat = bid >> 8;            // 0=q, 1=k, 2=v
    const float* W  = (mat == 0) ? Wq : (mat == 1) ? Wk : Wv;
    float* outg     = (mat == 0) ? g_q : (mat == 1) ? g_k : g_v;

    const int tid = threadIdx.x;
    const int fg  = tid & 31;
    const int tg  = tid >> 5;
    const int t0  = tg * 8;

    u64 acc[8][4];
    #pragma unroll
    for (int k = 0; k < 8; k++)
        #pragma unroll
        for (int p = 0; p < 4; p++) acc[k][p] = 0ull;

    const float* xb = x + (size_t)nb * (FF * TT);

    for (int c = 0; c < 8; c++) {
        const int f0 = c * 32;
        __syncthreads();
        {   // stage x chunk: rows f0..f0+31, contiguous 2048 floats
            const float4* s4 = (const float4*)(xb + f0 * TT);
            float4* d4 = (float4*)xs;
            d4[tid]       = s4[tid];
            d4[tid + 256] = s4[tid + 256];
        }
        {   // stage W chunk into ws[fl][h*32+d] with 257-pad rows
            #pragma unroll
            for (int m = 0; m < 8; m++) {
                int jj = tid + m * 256;            // 0..2047 (float4 index)
                int h  = jj >> 8;
                int r  = jj & 255;                 // float4 idx within h block
                int fl = r >> 3;
                int d0 = (r & 7) * 4;
                float4 wv = ((const float4*)(W + h * (FF * DD) + f0 * DD))[r];
                float* dst = ws + fl * 257 + h * 32 + d0;
                dst[0] = wv.x; dst[1] = wv.y; dst[2] = wv.z; dst[3] = wv.w;
            }
        }
        __syncthreads();

        #pragma unroll 2
        for (int fl = 0; fl < 32; fl++) {
            u64 xp[4];
            lds_v2u64(xs + fl * 64 + t0, xp[0], xp[1]);
            lds_v2u64(xs + fl * 64 + t0 + 4, xp[2], xp[3]);
            const float* wrow = ws + fl * 257 + fg;
            #pragma unroll
            for (int k = 0; k < 8; k++) {
                u64 wd = dup2(wrow[k * 32]);
                acc[k][0] = fma2(xp[0], wd, acc[k][0]);
                acc[k][1] = fma2(xp[1], wd, acc[k][1]);
                acc[k][2] = fma2(xp[2], wd, acc[k][2]);
                acc[k][3] = fma2(xp[3], wd, acc[k][3]);
            }
        }
    }

    // write: [h][n][b][t][d], h = k, d = fg; coalesced (lanes span d)
    const int n = nb >> 5, b = nb & 31;
    #pragma unroll
    for (int k = 0; k < 8; k++) {
        float* o = outg + (size_t)(((k * NA + n) * BB + b) * TT) * DD + fg;
        #pragma unroll
        for (int p = 0; p < 4; p++) {
            float a, bv; unpack2(acc[k][p], a, bv);
            o[(t0 + 2 * p)     * DD] = a;
            o[(t0 + 2 * p + 1) * DD] = bv;
        }
    }
}

// ======================== kernel 2: all-pairs attention ====================
// grid = 2048 (h*256 + j*32 + b), block = 256.
// q in smem (scaled); k/v prefetched to regs for i+1 during compute of i.
__global__ void __launch_bounds__(256, 2) attn_kernel()
{
    __shared__ __align__(16) float kT[DD * 66];    // [d][s], pad 66   8.4 KB
    __shared__ __align__(16) float vs[TT * DD];    // [s][d]           8 KB
    __shared__ __align__(16) float Ps[TT * 66];    // [t][s], pad 66  16.9 KB
    __shared__ __align__(16) float qs[TT * 33];    // [t][d], pad 33   8.4 KB

    const int bid = blockIdx.x;
    const int b = bid & 31, j = (bid >> 5) & 7, h = bid >> 8;
    const int tid = threadIdx.x;
    const int t0  = tid >> 3;       // rows t0 and t0+32
    const int c8  = tid & 7;        // 8-way column split

    // stage q (pre-scaled) into smem
    {
        const float* qb = g_q + (size_t)(((h * NA + j) * BB + b) * TT) * DD;
        #pragma unroll
        for (int r = 0; r < 8; r++) {
            int idx = tid + r * 256;
            int t = idx >> 5, d = idx & 31;
            qs[t * 33 + d] = qb[idx] * SCALE;
        }
    }

    u64 outA[2] = {0ull, 0ull}, outB[2] = {0ull, 0ull};

    const size_t kvstride4 = (size_t)BB * TT * DD / 4;   // float4 stride per i
    const float4* kb4 = (const float4*)(g_k + (size_t)((h * NA) * BB + b) * TT * DD);
    const float4* vb4 = (const float4*)(g_v + (size_t)((h * NA) * BB + b) * TT * DD);

    // prefetch i = 0
    float4 k4[2], v4[2];
    k4[0] = kb4[tid]; k4[1] = kb4[tid + 256];
    v4[0] = vb4[tid]; v4[1] = vb4[tid + 256];

    for (int i = 0; i < NA; i++) {
        __syncthreads();   // previous compute done -> buffers free; qs visible path
        {   // store staged k (transposed) and v
            #pragma unroll
            for (int m = 0; m < 2; m++) {
                int jj = tid + m * 256;
                int s = jj >> 3, d0 = (jj & 7) * 4;
                float4 kv = k4[m];
                kT[(d0 + 0) * 66 + s] = kv.x;
                kT[(d0 + 1) * 66 + s] = kv.y;
                kT[(d0 + 2) * 66 + s] = kv.z;
                kT[(d0 + 3) * 66 + s] = kv.w;
                ((float4*)vs)[jj] = v4[m];
            }
        }
        __syncthreads();

        if (i < NA - 1) {   // prefetch next i; latency hidden by compute below
            const float4* nk = kb4 + (size_t)(i + 1) * kvstride4;
            const float4* nv = vb4 + (size_t)(i + 1) * kvstride4;
            k4[0] = nk[tid]; k4[1] = nk[tid + 256];
            v4[0] = nv[tid]; v4[1] = nv[tid + 256];
        }

        // ---- S = q @ k^T : 4 s-pairs per row, rows t0 and t0+32 ----
        u64 sA[4] = {0ull,0ull,0ull,0ull}, sB[4] = {0ull,0ull,0ull,0ull};
        #pragma unroll 8
        for (int d = 0; d < DD; d++) {
            const u64* kr = (const u64*)(kT + d * 66);
            u64 k0 = kr[c8], k1 = kr[c8 + 8], k2 = kr[c8 + 16], k3 = kr[c8 + 24];
            u64 qda = dup2(qs[t0 * 33 + d]);
            u64 qdb = dup2(qs[(t0 + 32) * 33 + d]);
            sA[0] = fma2(k0, qda, sA[0]); sA[1] = fma2(k1, qda, sA[1]);
            sA[2] = fma2(k2, qda, sA[2]); sA[3] = fma2(k3, qda, sA[3]);
            sB[0] = fma2(k0, qdb, sB[0]); sB[1] = fma2(k1, qdb, sB[1]);
            sB[2] = fma2(k2, qdb, sB[2]); sB[3] = fma2(k3, qdb, sB[3]);
        }

        // ---- softmax over s (per key agent i) ----
        float eA[8], eB[8];
        #pragma unroll
        for (int m = 0; m < 4; m++) {
            unpack2(sA[m], eA[2*m], eA[2*m+1]);
            unpack2(sB[m], eB[2*m], eB[2*m+1]);
        }
        float mA = eA[0], mB = eB[0];
        #pragma unroll
        for (int p = 1; p < 8; p++) { mA = fmaxf(mA, eA[p]); mB = fmaxf(mB, eB[p]); }
        #pragma unroll
        for (int w = 1; w < 8; w <<= 1) {
            mA = fmaxf(mA, __shfl_xor_sync(0xffffffffu, mA, w));
            mB = fmaxf(mB, __shfl_xor_sync(0xffffffffu, mB, w));
        }
        float sumA = 0.f, sumB = 0.f;
        #pragma unroll
        for (int p = 0; p < 8; p++) {
            eA[p] = __expf(eA[p] - mA); sumA += eA[p];
            eB[p] = __expf(eB[p] - mB); sumB += eB[p];
        }
        #pragma unroll
        for (int w = 1; w < 8; w <<= 1) {
            sumA += __shfl_xor_sync(0xffffffffu, sumA, w);
            sumB += __shfl_xor_sync(0xffffffffu, sumB, w);
        }
        float invA = __frcp_rn(sumA), invB = __frcp_rn(sumB);

        float* Pa = Ps + t0 * 66;
        float* Pb = Ps + (t0 + 32) * 66;
        #pragma unroll
        for (int m = 0; m < 4; m++) {
            ((float2*)Pa)[c8 + 8*m] = make_float2(eA[2*m] * invA, eA[2*m+1] * invA);
            ((float2*)Pb)[c8 + 8*m] = make_float2(eB[2*m] * invB, eB[2*m+1] * invB);
        }
        __syncwarp();   // P rows are warp-local

        // ---- out += P @ V : this thread owns d = 4*c8 .. 4*c8+3 ----
        #pragma unroll 4
        for (int s2 = 0; s2 < 32; s2++) {
            float2 pA = ((const float2*)Pa)[s2];
            float2 pB = ((const float2*)Pb)[s2];
            u64 va0, va1, vb0, vb1;
            lds_v2u64(vs + (2 * s2)     * DD + 4 * c8, va0, va1);
            lds_v2u64(vs + (2 * s2 + 1) * DD + 4 * c8, vb0, vb1);
            u64 pA0 = dup2(pA.x), pA1 = dup2(pA.y);
            u64 pB0 = dup2(pB.x), pB1 = dup2(pB.y);
            outA[0] = fma2(va0, pA0, outA[0]); outA[1] = fma2(va1, pA0, outA[1]);
            outA[0] = fma2(vb0, pA1, outA[0]); outA[1] = fma2(vb1, pA1, outA[1]);
            outB[0] = fma2(va0, pB0, outB[0]); outB[1] = fma2(va1, pB0, outB[1]);
            outB[0] = fma2(vb0, pB1, outB[0]); outB[1] = fma2(vb1, pB1, outB[1]);
        }
        __syncwarp();
    }

    // write y[nb][h*32+d][t]
    const int nb = j * BB + b;
    float* yo = g_y + (size_t)(nb * FF + h * DD + 4 * c8) * TT + t0;
    float x0, x1, x2, x3;
    unpack2(outA[0], x0, x1); unpack2(outA[1], x2, x3);
    yo[0] = x0; yo[TT] = x1; yo[2*TT] = x2; yo[3*TT] = x3;
    unpack2(outB[0], x0, x1); unpack2(outB[1], x2, x3);
    float* yo2 = yo + 32;
    yo2[0] = x0; yo2[TT] = x1; yo2[2*TT] = x2; yo2[3*TT] = x3;
}

// ======================== kernel 3: output projection ======================
// grid = 256 (nb), block = 256.
// out[nb][g][t] = sum_f y[nb][f][t] * Wp[g][f] + bp[g]
// Thread (fg, tg): g = fg + 32k, t = tg*8..tg*8+7.
__global__ void __launch_bounds__(256, 2) proj_kernel(
    const float* __restrict__ Wp,
    const float* __restrict__ bp,
    float* __restrict__ out)
{
    __shared__ __align__(16) float ys[32 * 64];     // [fl][t]
    __shared__ __align__(16) float ws[32 * 257];    // [fl][g], 257-pad

    const int nb  = blockIdx.x;
    const int tid = threadIdx.x;
    const int fg  = tid & 31;
    const int tg  = tid >> 5;
    const int t0  = tg * 8;

    u64 acc[8][4];
    #pragma unroll
    for (int k = 0; k < 8; k++)
        #pragma unroll
        for (int p = 0; p < 4; p++) acc[k][p] = 0ull;

    const float* yb = g_y + (size_t)nb * (FF * TT);

    for (int c = 0; c < 8; c++) {
        const int f0 = c * 32;
        __syncthreads();
        {   // stage y chunk (contiguous)
            const float4* s4 = (const float4*)(yb + f0 * TT);
            float4* d4 = (float4*)ys;
            d4[tid]       = s4[tid];
            d4[tid + 256] = s4[tid + 256];
        }
        {   // stage Wp chunk transposed: ws[fl][g] = Wp[g][f0+fl]
            #pragma unroll
            for (int m = 0; m < 8; m++) {
                int jj = tid + m * 256;           // float4 index, 0..2047
                int g   = jj >> 3;
                int fl0 = (jj & 7) * 4;
                float4 wv = ((const float4*)(Wp + g * FF + f0))[jj & 7];
                ws[(fl0 + 0) * 257 + g] = wv.x;
                ws[(fl0 + 1) * 257 + g] = wv.y;
                ws[(fl0 + 2) * 257 + g] = wv.z;
                ws[(fl0 + 3) * 257 + g] = wv.w;
            }
        }
        __syncthreads();

        #pragma unroll 2
        for (int fl = 0; fl < 32; fl++) {
            u64 xp[4];
            lds_v2u64(ys + fl * 64 + t0, xp[0], xp[1]);
            lds_v2u64(ys + fl * 64 + t0 + 4, xp[2], xp[3]);
            const float* wrow = ws + fl * 257 + fg;
            #pragma unroll
            for (int k = 0; k < 8; k++) {
                u64 wd = dup2(wrow[k * 32]);
                acc[k][0] = fma2(xp[0], wd, acc[k][0]);
                acc[k][1] = fma2(xp[1], wd, acc[k][1]);
                acc[k][2] = fma2(xp[2], wd, acc[k][2]);
                acc[k][3] = fma2(xp[3], wd, acc[k][3]);
            }
        }
    }

    #pragma unroll
    for (int k = 0; k < 8; k++) {
        const int g = fg + 32 * k;
        const float bpv = bp[g];
        float* o = out + (size_t)(nb * FF + g) * TT + t0;
        #pragma unroll
        for (int p = 0; p < 4; p++) {
            float a, bv; unpack2(acc[k][p], a, bv);
            ((float2*)o)[p] = make_float2(a + bpv, bv + bpv);
        }
    }
}

// ======================== launch ==========================================
extern "C" void kernel_launch(void* const* d_in, const int* in_sizes, int n_in,
                              void* d_out, int out_size)
{
    (void)in_sizes; (void)n_in; (void)out_size;
    const float* x  = (const float*)d_in[0];
    const float* Wq = (const float*)d_in[1];
    const float* Wk = (const float*)d_in[2];
    const float* Wv = (const float*)d_in[3];
    const float* Wp = (const float*)d_in[4];
    const float* bp = (const float*)d_in[5];
    float* out = (float*)d_out;

    qkv_kernel<<<768, 256>>>(x, Wq, Wk, Wv);
    attn_kernel<<<2048, 256>>>();
    proj_kernel<<<256, 256>>>(Wp, bp, out);
}